// round 12
// baseline (speedup 1.0000x reference)
#include <cuda_runtime.h>
#include <math.h>

#define BB 32
#define TT 1024
#define DD 512
#define HH 512
#define HP 516
#define WPT 516
#define RP0 20
#define RP1 12

// ---------------- scratch (device globals: allocation-free) ----------------
__device__ float g_pre[TT * BB * HH];   // layer-0 input transform + bias, [t][b][j]
__device__ float g_h0[2][BB][HH];       // layer-0 hidden double buffer
__device__ float g_h1[2][BB][HH];       // layer-1 hidden double buffer
__device__ unsigned g_c0[4 * 32];       // per-bg h0 arrival counters (128B apart)
__device__ unsigned g_c1[4 * 32];       // per-bg h1 arrival counters

// ---------------- helpers ----------------------------------------------------
__device__ __forceinline__ unsigned ldacq(const unsigned* p) {
    unsigned v;
    asm volatile("ld.acquire.gpu.u32 %0, [%1];" : "=r"(v) : "l"(p) : "memory");
    return v;
}
__device__ __forceinline__ void red_rel(unsigned* p) {
    asm volatile("red.release.gpu.global.add.u32 [%0], 1;" :: "l"(p) : "memory");
}
__device__ __forceinline__ void fma2(unsigned long long& d,
                                     unsigned long long a, unsigned long long b) {
    asm("fma.rn.f32x2 %0, %1, %2, %0;" : "+l"(d) : "l"(a), "l"(b));
}
__device__ __forceinline__ unsigned long long packf2(float x, float y) {
    return (unsigned long long)__float_as_uint(x)
         | ((unsigned long long)__float_as_uint(y) << 32);
}
#define BARS(id, n) asm volatile("bar.sync %0, %1;" :: "r"(id), "r"(n) : "memory")
#define BARA(id, n) asm volatile("bar.arrive %0, %1;" :: "r"(id), "r"(n) : "memory")

// ---------------- init: zero recurrent state + counters ----------------------
__global__ void init_state() {
    int idx = blockIdx.x * blockDim.x + threadIdx.x;
    if (idx < 2 * BB * HH) {
        ((float*)g_h0)[idx] = 0.f;
        ((float*)g_h1)[idx] = 0.f;
    }
    if (idx < 4 * 32) { g_c0[idx] = 0; g_c1[idx] = 0; }
}

// ---------------- pre-GEMM (layer 0 only), f32x2 packed along k --------------
__global__ __launch_bounds__(256) void gemm_pre(
    const float* __restrict__ X, const float* __restrict__ W,
    const float* __restrict__ b1, const float* __restrict__ b2)
{
    __shared__ unsigned long long As2[8][66];
    __shared__ unsigned long long Bs2[8][66];

    const int m0 = blockIdx.y * 64;
    const int n0 = blockIdx.x * 64;
    const int tid = threadIdx.x;
    const int r  = tid >> 2;
    const int kq = tid & 3;
    const int tx = tid & 15;
    const int ty = tid >> 4;

    const int m = m0 + r;
    const int t = m >> 5, b = m & 31;
    const float* arow = X + ((size_t)b * TT + t) * DD;
    const float* brow = W + (size_t)(n0 + r) * DD;

    unsigned long long acc2[4][4];
#pragma unroll
    for (int i = 0; i < 4; i++)
#pragma unroll
        for (int j = 0; j < 4; j++) acc2[i][j] = 0ull;

    float4 a_next = *(const float4*)(arow + kq * 4);
    float4 b_next = *(const float4*)(brow + kq * 4);

    for (int kt = 0; kt < DD / 16; kt++) {
        float4 a = a_next, bv = b_next;
        As2[kq * 2 + 0][r] = packf2(a.x, a.y);
        As2[kq * 2 + 1][r] = packf2(a.z, a.w);
        Bs2[kq * 2 + 0][r] = packf2(bv.x, bv.y);
        Bs2[kq * 2 + 1][r] = packf2(bv.z, bv.w);
        __syncthreads();
        if (kt + 1 < DD / 16) {
            a_next = *(const float4*)(arow + (kt + 1) * 16 + kq * 4);
            b_next = *(const float4*)(brow + (kt + 1) * 16 + kq * 4);
        }
#pragma unroll
        for (int k2 = 0; k2 < 8; k2++) {
            ulonglong2 a01 = *(const ulonglong2*)&As2[k2][ty * 4];
            ulonglong2 a23 = *(const ulonglong2*)&As2[k2][ty * 4 + 2];
            ulonglong2 b01 = *(const ulonglong2*)&Bs2[k2][tx * 4];
            ulonglong2 b23 = *(const ulonglong2*)&Bs2[k2][tx * 4 + 2];
            unsigned long long am[4] = {a01.x, a01.y, a23.x, a23.y};
            unsigned long long bn[4] = {b01.x, b01.y, b23.x, b23.y};
#pragma unroll
            for (int i = 0; i < 4; i++)
#pragma unroll
                for (int j = 0; j < 4; j++) fma2(acc2[i][j], am[i], bn[j]);
        }
        __syncthreads();
    }

    float bias[4];
#pragma unroll
    for (int j = 0; j < 4; j++) {
        int n = n0 + tx * 4 + j;
        bias[j] = b1[n] + b2[n];
    }
#pragma unroll
    for (int i = 0; i < 4; i++) {
        int mo = m0 + ty * 4 + i;
        float4 v;
        float s[4];
#pragma unroll
        for (int j = 0; j < 4; j++) {
            unsigned long long acc = acc2[i][j];
            s[j] = __uint_as_float((unsigned)acc)
                 + __uint_as_float((unsigned)(acc >> 32)) + bias[j];
        }
        v.x = s[0]; v.y = s[1]; v.z = s[2]; v.w = s[3];
        *(float4*)&g_pre[(size_t)mo * HH + n0 + tx * 4] = v;
    }
}

// ---------------- warp-specialized fused recurrence --------------------------
// 128 CTAs = 32 j-groups (16 rows) x 4 batch-groups (8 batches). 384 threads.
// G0 (warps 0-7, 256 thr): h0 chain, Whh0 in regs, 2 warps/SMSP (priority).
// G1 (warps 8-11, 128 thr): mat1 (Wih1) + mat2 (Whh1) from SMEM + h1 chain.
// bar1 (384): G0 arrives post-stage, G1 syncs.
// bar7 (384): G1 arrives after mat1 (its Hs0 reads); G0 syncs pre-overwrite.
//             G0 primes one phase pre-loop (G0-sync@r pairs G1-arrive@r-1).
#define SMEM_WS ((32*WPT + 2*8*HP + 8*HP + 128*RP0 + 2*128*RP1 + 32) * 4)

__global__ __launch_bounds__(384, 1) void rnn_ws(
    const float* __restrict__ Whh0, const float* __restrict__ Wih1,
    const float* __restrict__ Whh1, const float* __restrict__ bih1,
    const float* __restrict__ bhh1, float* __restrict__ out)
{
    extern __shared__ float sm[];
    float* Wsm  = sm;                    // 32 x WPT (16 Wih1, 16 Whh1)
    float* Hs0  = Wsm + 32 * WPT;        // 2 bufs x 8 x HP
    float* Hs1  = Hs0 + 2 * 8 * HP;      // 8 x HP
    float* red0 = Hs1 + 8 * HP;          // 128 x RP0
    float* red1 = red0 + 128 * RP0;      // 128 x RP1
    float* red2 = red1 + 128 * RP1;      // 128 x RP1
    float* b1s  = red2 + 128 * RP1;      // 16

    const int tid  = threadIdx.x;
    const int wid  = tid >> 5;
    const int lane = tid & 31;
    const int bg = blockIdx.x >> 5;      // 0..3
    const int jg = blockIdx.x & 31;      // 0..31

    const int jq  = lane & 3;
    const int ksl = lane >> 2;           // 0..7

    // ---- cooperative loads: Wsm (mats 1,2) + bias + prezero h tiles --------
    for (int i = tid; i < 32 * 128; i += 384) {
        int row = i >> 7, c = i & 127;
        const float* src = (row < 16)
            ? Wih1 + (size_t)(jg * 16 + row) * HH
            : Whh1 + (size_t)(jg * 16 + row - 16) * HH;
        *(float4*)&Wsm[row * WPT + c * 4] = *(const float4*)(src + c * 4);
    }
    for (int i = tid; i < 3 * 8 * HP; i += 384) Hs0[i] = 0.f;   // Hs0 x2 + Hs1
    if (tid < 16) b1s[tid] = bih1[jg * 16 + tid] + bhh1[jg * 16 + tid];
    __syncthreads();

    unsigned* cnt0 = &g_c0[bg * 32];
    unsigned* cnt1 = &g_c1[bg * 32];

    const int crow = tid & 127;
    const int eb = crow >> 4, ej = crow & 15;
    const int gb = bg * 8 + eb;
    const int gj = jg * 16 + ej;
    const size_t HIDOFF = (size_t)BB * TT * HH;

    if (tid < 256) {
        // ======================= G0: h0 chain ===============================
        const int w8 = wid;                  // 0..7
        const int ks = w8 * 8 + ksl;         // 0..63, 8-float slice
        unsigned long long wreg[4][4];
#pragma unroll
        for (int jj = 0; jj < 4; jj++) {
            const float* wr = Whh0 + (size_t)(jg * 16 + jq * 4 + jj) * HH + ks * 8;
#pragma unroll
            for (int c = 0; c < 4; c++)
                wreg[jj][c] = *(const unsigned long long*)(wr + c * 2);
        }

        BARA(7, 384);                        // prime bar7
        float pv = g_pre[((size_t)0 * BB + gb) * HH + gj];

        for (int r = 0; r <= TT; r++) {
            float* Hb = Hs0 + (r & 1) * 8 * HP;
            if (r > 0) {
                if (lane == 0) { while (ldacq(cnt0) < (unsigned)(32 * r)) { } }
                __syncwarp();
                if (r >= 2) BARS(7, 384);    // G1 done with this buffer
                // stage h0[r-1]: 8KB over 256 threads
#pragma unroll
                for (int it = 0; it < 4; it++) {
                    int idx = it * 256 + tid;
                    if (idx < 1024) {
                        int b = idx >> 7, c = idx & 127;
                        *(float4*)&Hb[b * HP + c * 4] =
                            *(const float4*)&g_h0[(r - 1) & 1][bg * 8 + b][c * 4];
                    }
                }
            }
            BARA(1, 384);                    // publish Hs0 to G1
            BARS(2, 256);                    // staging visible within G0

            if (r < TT) {
                unsigned long long acc[4][8];
#pragma unroll
                for (int a = 0; a < 4; a++)
#pragma unroll
                    for (int b = 0; b < 8; b++) acc[a][b] = 0ull;
#pragma unroll
                for (int i = 0; i < 2; i++) {
#pragma unroll
                    for (int b = 0; b < 8; b++) {
                        ulonglong2 h2 = *(const ulonglong2*)&Hb[b * HP + ks * 8 + i * 4];
#pragma unroll
                        for (int jj = 0; jj < 4; jj++) {
                            fma2(acc[jj][b], wreg[jj][2 * i],     h2.x);
                            fma2(acc[jj][b], wreg[jj][2 * i + 1], h2.y);
                        }
                    }
                }
                float part[4][8];
#pragma unroll
                for (int jj = 0; jj < 4; jj++)
#pragma unroll
                    for (int b = 0; b < 8; b++) {
                        unsigned long long v = acc[jj][b];
                        part[jj][b] = __uint_as_float((unsigned)v)
                                    + __uint_as_float((unsigned)(v >> 32));
                    }
                // fold ksl bits 1,2 (masks 8,16): reps have ksl in {0,1}
#pragma unroll
                for (int m = 8; m <= 16; m <<= 1)
#pragma unroll
                    for (int jj = 0; jj < 4; jj++)
#pragma unroll
                        for (int b = 0; b < 8; b++)
                            part[jj][b] += __shfl_xor_sync(0xffffffffu, part[jj][b], m);
                if (ksl < 2) {
#pragma unroll
                    for (int jj = 0; jj < 4; jj++)
#pragma unroll
                        for (int b = 0; b < 8; b++)
                            red0[(b * 16 + jq * 4 + jj) * RP0 + w8 * 2 + ksl]
                                = part[jj][b];
                }
            }
            BARS(3, 256);                    // red0 ready
            if (r < TT && tid < 128) {
                const float* rb = red0 + crow * RP0;
                float4 p0 = *(const float4*)(rb);
                float4 p1 = *(const float4*)(rb + 4);
                float4 p2 = *(const float4*)(rb + 8);
                float4 p3 = *(const float4*)(rb + 12);
                float s = pv + (p0.x + p0.y + p0.z + p0.w)
                             + (p1.x + p1.y + p1.z + p1.w)
                             + (p2.x + p2.y + p2.z + p2.w)
                             + (p3.x + p3.y + p3.z + p3.w);
                float hn = tanhf(s);
                g_h0[r & 1][gb][gj] = hn;
                if (r == TT - 1) out[HIDOFF + (size_t)gb * HH + gj] = hn;
                if (r + 1 < TT) pv = g_pre[((size_t)(r + 1) * BB + gb) * HH + gj];
            }
            BARS(8, 256);                    // h0 stores done
            if (r < TT && tid == 0) red_rel(cnt0);
        }
    } else {
        // ======================= G1: mat1 + mat2 + h1 =======================
        const int ltid = tid - 256;          // 0..127
        const int w4 = wid - 8;              // 0..3
        const int ks = w4 * 8 + ksl;         // 0..31, 16-float slice

        for (int r = 0; r <= TT; r++) {
            float* Hb = Hs0 + (r & 1) * 8 * HP;
            if (r >= 2) {
                if (lane == 0) { while (ldacq(cnt1) < (unsigned)(32 * (r - 1))) { } }
                __syncwarp();
                // stage h1[r-2]: 8KB over 128 threads
#pragma unroll
                for (int it = 0; it < 8; it++) {
                    int idx = it * 128 + ltid;
                    int b = idx >> 7, c = idx & 127;
                    *(float4*)&Hs1[b * HP + c * 4] =
                        *(const float4*)&g_h1[(r - 2) & 1][bg * 8 + b][c * 4];
                }
            }
            BARS(6, 128);                    // Hs1 visible within G1
            BARS(1, 384);                    // wait Hs0 staged by G0

            // ---- mat1: Wih1 @ h0[r-1] ----
            {
                unsigned long long acc[4][8];
#pragma unroll
                for (int a = 0; a < 4; a++)
#pragma unroll
                    for (int b = 0; b < 8; b++) acc[a][b] = 0ull;
#pragma unroll
                for (int i = 0; i < 4; i++) {
                    ulonglong2 h2[8];
#pragma unroll
                    for (int b = 0; b < 8; b++)
                        h2[b] = *(const ulonglong2*)&Hb[b * HP + ks * 16 + i * 4];
#pragma unroll
                    for (int jj = 0; jj < 4; jj++) {
                        ulonglong2 w2 = *(const ulonglong2*)
                            &Wsm[(jq * 4 + jj) * WPT + ks * 16 + i * 4];
#pragma unroll
                        for (int b = 0; b < 8; b++) {
                            fma2(acc[jj][b], w2.x, h2[b].x);
                            fma2(acc[jj][b], w2.y, h2[b].y);
                        }
                    }
                }
                BARA(7, 384);                // done reading Hs0 buffer r&1
                float part[4][8];
#pragma unroll
                for (int jj = 0; jj < 4; jj++)
#pragma unroll
                    for (int b = 0; b < 8; b++) {
                        unsigned long long v = acc[jj][b];
                        part[jj][b] = __uint_as_float((unsigned)v)
                                    + __uint_as_float((unsigned)(v >> 32));
                    }
#pragma unroll
                for (int m = 4; m <= 16; m <<= 1)
#pragma unroll
                    for (int jj = 0; jj < 4; jj++)
#pragma unroll
                        for (int b = 0; b < 8; b++)
                            part[jj][b] += __shfl_xor_sync(0xffffffffu, part[jj][b], m);
                if (ksl == 0)
#pragma unroll
                    for (int jj = 0; jj < 4; jj++)
#pragma unroll
                        for (int b = 0; b < 8; b++)
                            red1[(b * 16 + jq * 4 + jj) * RP1 + w4] = part[jj][b];
            }

            // ---- mat2: Whh1 @ h1[r-2] ----
            {
                unsigned long long acc[4][8];
#pragma unroll
                for (int a = 0; a < 4; a++)
#pragma unroll
                    for (int b = 0; b < 8; b++) acc[a][b] = 0ull;
#pragma unroll
                for (int i = 0; i < 4; i++) {
                    ulonglong2 h2[8];
#pragma unroll
                    for (int b = 0; b < 8; b++)
                        h2[b] = *(const ulonglong2*)&Hs1[b * HP + ks * 16 + i * 4];
#pragma unroll
                    for (int jj = 0; jj < 4; jj++) {
                        ulonglong2 w2 = *(const ulonglong2*)
                            &Wsm[(16 + jq * 4 + jj) * WPT + ks * 16 + i * 4];
#pragma unroll
                        for (int b = 0; b < 8; b++) {
                            fma2(acc[jj][b], w2.x, h2[b].x);
                            fma2(acc[jj][b], w2.y, h2[b].y);
                        }
                    }
                }
                float part[4][8];
#pragma unroll
                for (int jj = 0; jj < 4; jj++)
#pragma unroll
                    for (int b = 0; b < 8; b++) {
                        unsigned long long v = acc[jj][b];
                        part[jj][b] = __uint_as_float((unsigned)v)
                                    + __uint_as_float((unsigned)(v >> 32));
                    }
#pragma unroll
                for (int m = 4; m <= 16; m <<= 1)
#pragma unroll
                    for (int jj = 0; jj < 4; jj++)
#pragma unroll
                        for (int b = 0; b < 8; b++)
                            part[jj][b] += __shfl_xor_sync(0xffffffffu, part[jj][b], m);
                if (ksl == 0)
#pragma unroll
                    for (int jj = 0; jj < 4; jj++)
#pragma unroll
                        for (int b = 0; b < 8; b++)
                            red2[(b * 16 + jq * 4 + jj) * RP1 + w4] = part[jj][b];
            }

            BARS(4, 128);                    // red1+red2 ready
            if (r >= 1) {
                const int t1 = r - 1;
                float4 p1 = *(const float4*)&red1[crow * RP1];
                float4 p2 = *(const float4*)&red2[crow * RP1];
                float hn = tanhf(b1s[ej] + p1.x + p1.y + p1.z + p1.w
                                         + p2.x + p2.y + p2.z + p2.w);
                g_h1[t1 & 1][gb][gj] = hn;
                out[((size_t)gb * TT + t1) * HH + gj] = hn;
                if (t1 == TT - 1)
                    out[HIDOFF + (size_t)BB * HH + (size_t)gb * HH + gj] = hn;
            }
            BARS(5, 128);                    // h1 stores done
            if (r >= 1 && r < TT && ltid == 0) red_rel(cnt1);
        }
    }
}

// ---------------- launch ----------------------------------------------------
extern "C" void kernel_launch(void* const* d_in, const int* in_sizes, int n_in,
                              void* d_out, int out_size)
{
    (void)in_sizes; (void)n_in; (void)out_size;
    const float* x    = (const float*)d_in[0];
    const float* wih0 = (const float*)d_in[1];
    const float* whh0 = (const float*)d_in[2];
    const float* bih0 = (const float*)d_in[3];
    const float* bhh0 = (const float*)d_in[4];
    const float* wih1 = (const float*)d_in[5];
    const float* whh1 = (const float*)d_in[6];
    const float* bih1 = (const float*)d_in[7];
    const float* bhh1 = (const float*)d_in[8];
    float* out = (float*)d_out;

    cudaFuncSetAttribute(rnn_ws,
                         cudaFuncAttributeMaxDynamicSharedMemorySize, SMEM_WS);

    init_state<<<128, 256>>>();

    dim3 gemmGrid(HH / 64, (TT * BB) / 64);   // (8, 512)
    gemm_pre<<<gemmGrid, 256>>>(x, wih0, bih0, bhh0);

    rnn_ws<<<128, 384, SMEM_WS>>>(whh0, wih1, whh1, bih1, bhh1, out);
}